// round 15
// baseline (speedup 1.0000x reference)
#include <cuda_runtime.h>
#include <cuda_bf16.h>
#include <cuda_fp16.h>
#include <math.h>
#include <stdint.h>

#define NNODES 100000
#define NEDGES 1600000
#define FIN 256
#define HID 128
#define COUT 64

#define SCAN_TPB 256
#define SCAN_ELEMS 8
#define SCAN_CHUNK (SCAN_TPB * SCAN_ELEMS)                 // 2048
#define SCAN_NB ((NNODES + SCAN_CHUNK - 1) / SCAN_CHUNK)   // 49

// ---------------- scratch (static __device__, no allocation) ----------------
__device__ __half g_tmp[NNODES * HID];          // messages (GEMM out), fp16
__device__ __half g_hf[NNODES * HID];           // relu'd h fp16 (GEMM A) / h3 fp16 copy
__device__ __half g_pf[NNODES * HID];           // pre-relu h2 fp16 (gram operand)
__device__ float g_dinv[NNODES];
__device__ int   g_cnt[NNODES];
__device__ int   g_cursor[NNODES];
__device__ int   g_rowptr[NNODES + 1];
__device__ int   g_col[NEDGES];
__device__ float g_w[NEDGES];
__device__ float g_G[HID * HID];
__device__ float g_csum[HID];
__device__ float g_G2[COUT * COUT];
__device__ float g_csum2[COUT];
__device__ int   g_bsum[SCAN_NB];

// split-fp16 transposed weights: Wt[d][k] = W[k][d]
__device__ __half g_w0h[HID * FIN],  g_w0l[HID * FIN];
__device__ __half g_w1h[HID * HID],  g_w1l[HID * HID];
__device__ __half g_w2h[HID * HID],  g_w2l[HID * HID];
__device__ __half g_w3h[COUT * HID], g_w3l[COUT * HID];

// ---------------- helpers ----------------
__device__ __forceinline__ uint32_t smem_u32(const void* p) {
    uint32_t a;
    asm("{ .reg .u64 t; cvta.to.shared.u64 t, %1; cvt.u32.u64 %0, t; }"
        : "=r"(a) : "l"(p));
    return a;
}
__device__ __forceinline__ uint32_t sw128(uint32_t off) {
    return off ^ ((off >> 3) & 0x70);
}
__device__ __forceinline__ void ldsm4(uint32_t* r, uint32_t addr) {
    asm volatile("ldmatrix.sync.aligned.m8n8.x4.shared.b16 {%0,%1,%2,%3}, [%4];"
                 : "=r"(r[0]), "=r"(r[1]), "=r"(r[2]), "=r"(r[3]) : "r"(addr));
}
__device__ __forceinline__ void mma_h(float* c, const uint32_t* a,
                                      const uint32_t* b) {
    asm volatile(
        "mma.sync.aligned.m16n8k16.row.col.f32.f16.f16.f32 "
        "{%0,%1,%2,%3}, {%4,%5,%6,%7}, {%8,%9}, {%0,%1,%2,%3};"
        : "+f"(c[0]), "+f"(c[1]), "+f"(c[2]), "+f"(c[3])
        : "r"(a[0]), "r"(a[1]), "r"(a[2]), "r"(a[3]), "r"(b[0]), "r"(b[1]));
}
__device__ __forceinline__ void split2h(float f, __half& h, __half& l) {
    h = __float2half_rn(f);
    l = __float2half_rn(f - __half2float(h));
}
__device__ __forceinline__ void cpa16(uint32_t dst, const void* src, int nbytes) {
    asm volatile("cp.async.cg.shared.global [%0], [%1], 16, %2;"
                 :: "r"(dst), "l"(src), "r"(nbytes) : "memory");
}
__device__ __forceinline__ void cpa_commit() {
    asm volatile("cp.async.commit_group;" ::: "memory");
}
__device__ __forceinline__ void cpa_wait1() {
    asm volatile("cp.async.wait_group 1;" ::: "memory");
}
__device__ __forceinline__ void cpa_wait0() {
    asm volatile("cp.async.wait_group 0;" ::: "memory");
}

// ---------------- preprocessing ----------------
__global__ void k_count(const int* __restrict__ ei) {
    int e = blockIdx.x * blockDim.x + threadIdx.x;
    if (e < NEDGES) atomicAdd(&g_cnt[ei[e]], 1);
}

__global__ void k_scan1() {
    __shared__ int warp_s[SCAN_TPB / 32];
    int tid = threadIdx.x, blk = blockIdx.x;
    int base = blk * SCAN_CHUNK + tid * SCAN_ELEMS;
    int s = 0;
#pragma unroll
    for (int i = 0; i < SCAN_ELEMS; i++) {
        int idx = base + i;
        if (idx < NNODES) {
            int c = g_cnt[idx];
            s += c;
            g_dinv[idx] = rsqrtf((float)(c + 1));  // +1 self loop
        }
    }
    for (int o = 16; o > 0; o >>= 1) s += __shfl_down_sync(0xffffffffu, s, o);
    if ((tid & 31) == 0) warp_s[tid >> 5] = s;
    __syncthreads();
    if (tid < SCAN_TPB / 32) {
        int w = warp_s[tid];
        for (int o = (SCAN_TPB / 64); o > 0; o >>= 1)
            w += __shfl_down_sync(0xffu, w, o);
        if (tid == 0) g_bsum[blk] = w;
    }
}

__global__ void k_scan2() {
    __shared__ int sh[64];
    int tid = threadIdx.x;
    sh[tid] = (tid < SCAN_NB) ? g_bsum[tid] : 0;
    __syncthreads();
    for (int o = 1; o < 64; o <<= 1) {
        int v = (tid >= o) ? sh[tid - o] : 0;
        __syncthreads();
        sh[tid] += v;
        __syncthreads();
    }
    if (tid < SCAN_NB) g_bsum[tid] = (tid == 0) ? 0 : sh[tid - 1];
    if (tid == 0) g_rowptr[NNODES] = sh[SCAN_NB - 1];
}

__global__ void k_scan3() {
    __shared__ int tsum[SCAN_TPB];
    int tid = threadIdx.x, blk = blockIdx.x;
    int base = blk * SCAN_CHUNK + tid * SCAN_ELEMS;
    int c[SCAN_ELEMS];
    int s = 0;
#pragma unroll
    for (int i = 0; i < SCAN_ELEMS; i++) {
        int idx = base + i;
        c[i] = (idx < NNODES) ? g_cnt[idx] : 0;
        s += c[i];
    }
    tsum[tid] = s;
    __syncthreads();
    for (int o = 1; o < SCAN_TPB; o <<= 1) {
        int v = (tid >= o) ? tsum[tid - o] : 0;
        __syncthreads();
        tsum[tid] += v;
        __syncthreads();
    }
    int run = g_bsum[blk] + ((tid == 0) ? 0 : tsum[tid - 1]);
#pragma unroll
    for (int i = 0; i < SCAN_ELEMS; i++) {
        int idx = base + i;
        if (idx < NNODES) { g_rowptr[idx] = run; run += c[i]; }
    }
}

__global__ void k_fill(const int* __restrict__ ei) {
    int e = blockIdx.x * blockDim.x + threadIdx.x;
    if (e >= NEDGES) return;
    int r = ei[e];
    int c = ei[NEDGES + e];
    int pos = g_rowptr[r] + atomicAdd(&g_cursor[r], 1);
    g_col[pos] = c;
    g_w[pos] = g_dinv[r] * g_dinv[c];
}

// ---------------- weight prep: W[K,D] fp32 -> Wt hi/lo fp16 [D][K] ----------
template <int K, int D>
__global__ void k_prepW(const float* __restrict__ W,
                        __half* __restrict__ Wh, __half* __restrict__ Wl) {
    int i = blockIdx.x * blockDim.x + threadIdx.x;
    if (i >= K * D) return;
    int n = i / K, k = i % K;
    __half h, l;
    split2h(W[k * D + n], h, l);
    Wh[n * K + k] = h;
    Wl[n * K + k] = l;
}

__global__ void k_prepW3x(const float* __restrict__ W1,
                          const float* __restrict__ W2,
                          const float* __restrict__ W3) {
    int i = blockIdx.x * blockDim.x + threadIdx.x;
    const int S1 = HID * HID, S2 = 2 * HID * HID, S3 = 2 * HID * HID + HID * COUT;
    __half h, l;
    if (i < S1) {
        int n = i / HID, k = i % HID;
        split2h(W1[k * HID + n], h, l);
        g_w1h[n * HID + k] = h; g_w1l[n * HID + k] = l;
    } else if (i < S2) {
        int j = i - S1;
        int n = j / HID, k = j % HID;
        split2h(W2[k * HID + n], h, l);
        g_w2h[n * HID + k] = h; g_w2l[n * HID + k] = l;
    } else if (i < S3) {
        int j = i - S2;
        int n = j / HID, k = j % HID;
        split2h(W3[k * COUT + n], h, l);
        g_w3h[n * HID + k] = h; g_w3l[n * HID + k] = l;
    }
}

// ---------------- fp16-A / split-fp16-B GEMM --------------------------------
template <int K, int D, bool CONVERT, int MINB>
__global__ __launch_bounds__(512, MINB) void k_tgemm512(const float* __restrict__ Af,
                                                        const __half* __restrict__ Ah,
                                                        const __half* __restrict__ Bh,
                                                        const __half* __restrict__ Bl,
                                                        __half* __restrict__ C) {
    extern __shared__ __align__(1024) uint8_t smem[];
    const int CK = 64;
    const int NCH = K / CK;
    const int WN = D / 4;
    const int NT = WN / 8;
    const int STA = 128 * 128;
    const int SBB = D * 128;
    const bool SINGLE = (!CONVERT) && (NCH <= 2);
    const int NSTA = SINGLE ? NCH : 2;
    const int OFF_B = NSTA * STA;

    uint32_t sb = smem_u32(smem);
    int tid = threadIdx.x, wid = tid >> 5, lane = tid & 31;
    int wm = wid & 3, wn = wid >> 2;
    int row0 = wm * 32;
    int col0 = wn * WN;
    int grow = blockIdx.x * 128;

    float acc[2][NT][4];
#pragma unroll
    for (int i = 0; i < 2; i++)
#pragma unroll
        for (int j = 0; j < NT; j++)
#pragma unroll
            for (int q = 0; q < 4; q++) acc[i][j][q] = 0.f;

    auto a_async = [&](int s, int ch) {
        int kk = ch * CK;
#pragma unroll
        for (int i = 0; i < 2; i++) {
            int u = tid + i * 512;
            int m = u >> 3, g = u & 7;
            int r = grow + m;
            int rc = (r < NNODES) ? r : 0;
            int nb = (r < NNODES) ? 16 : 0;
            uint32_t so = sw128((uint32_t)(m * 128 + g * 16));
            cpa16(sb + s * STA + so, &Ah[(size_t)rc * K + kk + g * 8], nb);
        }
    };
    auto b_async = [&](int s, int ch) {
        int kk = ch * CK;
#pragma unroll
        for (int i = 0; i < (D * 8 + 511) / 512; i++) {
            int u = tid + i * 512;
            if (u < D * 8) {
                int n = u >> 3, g = u & 7;
                uint32_t so = sw128((uint32_t)(n * 128 + g * 16));
                cpa16(sb + OFF_B + (2 * s) * SBB + so, &Bh[n * K + kk + g * 8], 16);
                cpa16(sb + OFF_B + (2 * s + 1) * SBB + so, &Bl[n * K + kk + g * 8], 16);
            }
        }
    };
    auto a_direct = [&](int s, int ch) {
        int kk = ch * CK;
#pragma unroll
        for (int i = 0; i < 2; i++) {
            int u = tid + i * 512;
            int m = u >> 3, g = u & 7;
            int r = grow + m;
            float4 v0 = make_float4(0.f, 0.f, 0.f, 0.f), v1 = v0;
            if (r < NNODES) {
                const float* p = &Af[(size_t)r * K + kk + g * 8];
                v0 = *(const float4*)p;
                v1 = *(const float4*)(p + 4);
            }
            __half2 h0 = __floats2half2_rn(v0.x, v0.y);
            __half2 h1 = __floats2half2_rn(v0.z, v0.w);
            __half2 h2 = __floats2half2_rn(v1.x, v1.y);
            __half2 h3 = __floats2half2_rn(v1.z, v1.w);
            uint32_t so = sw128((uint32_t)(m * 128 + g * 16));
            *(uint4*)(smem + s * STA + so) =
                make_uint4(*(uint32_t*)&h0, *(uint32_t*)&h1,
                           *(uint32_t*)&h2, *(uint32_t*)&h3);
        }
    };
    auto mma_stage = [&](int stA, int stB) {
        uint32_t aB = sb + stA * STA;
        uint32_t bB0 = sb + OFF_B + (2 * stB) * SBB;
        uint32_t bB1 = sb + OFF_B + (2 * stB + 1) * SBB;
#pragma unroll
        for (int k16 = 0; k16 < CK / 16; k16++) {
            int kb = k16 * 32;
            uint32_t ah[2][4];
#pragma unroll
            for (int mt = 0; mt < 2; mt++) {
                int r = row0 + mt * 16 + (lane & 15);
                int cb = kb + ((lane & 16) ? 16 : 0);
                uint32_t so = sw128((uint32_t)(r * 128 + cb));
                ldsm4(ah[mt], aB + so);
            }
#pragma unroll
            for (int bt = 0; bt < NT / 2; bt++) {
                int n = col0 + bt * 16 + (lane & 7) + ((lane & 16) ? 8 : 0);
                int cb = kb + ((lane & 8) ? 16 : 0);
                uint32_t so = sw128((uint32_t)(n * 128 + cb));
                uint32_t bh[4], bl[4];
                ldsm4(bh, bB0 + so);
                ldsm4(bl, bB1 + so);
#pragma unroll
                for (int h = 0; h < 2; h++) {
                    int nt = bt * 2 + h;
#pragma unroll
                    for (int mt = 0; mt < 2; mt++) {
                        mma_h(acc[mt][nt], ah[mt], &bh[h * 2]);
                        mma_h(acc[mt][nt], ah[mt], &bl[h * 2]);
                    }
                }
            }
        }
    };

    if (SINGLE) {
#pragma unroll
        for (int s = 0; s < NCH; s++) { a_async(s, s); b_async(s, s); }
        cpa_commit();
        cpa_wait0();
        __syncthreads();
#pragma unroll
        for (int ch = 0; ch < NCH; ch++) mma_stage(ch, ch);
    } else {
        a_direct(0, 0);
        b_async(0, 0);
        cpa_commit();
        for (int ch = 0; ch < NCH; ch++) {
            int cur = ch & 1, nxt = cur ^ 1;
            bool more = (ch + 1 < NCH);
            if (more) {
                b_async(nxt, ch + 1);
                cpa_commit();
            }
            if (more) cpa_wait1(); else cpa_wait0();
            __syncthreads();
            mma_stage(cur, cur);
            if (more) a_direct(nxt, ch + 1);
            __syncthreads();
        }
    }

#pragma unroll
    for (int mt = 0; mt < 2; mt++) {
        int r0 = grow + row0 + mt * 16 + (lane >> 2);
        int r1 = r0 + 8;
#pragma unroll
        for (int nt = 0; nt < NT; nt++) {
            int cc = col0 + nt * 8 + (lane & 3) * 2;
            if (r0 < NNODES)
                *(__half2*)&C[(size_t)r0 * D + cc] =
                    __floats2half2_rn(acc[mt][nt][0], acc[mt][nt][1]);
            if (r1 < NNODES)
                *(__half2*)&C[(size_t)r1 * D + cc] =
                    __floats2half2_rn(acc[mt][nt][2], acc[mt][nt][3]);
        }
    }
}

// ---------------- sparse aggregation (fp16 gather, fp32 accumulate) --------
// Predicated full-width batches: every iteration issues 8 independent
// gathers (out-of-range slots clamp to edge e with weight 0) so the tail
// edges run at the same MLP as the body.
template <bool PRE>
__global__ void k_agg128s(const __half* __restrict__ tmp,
                          __half* __restrict__ hf,
                          __half* __restrict__ pfh) {
    int gw = (blockIdx.x * blockDim.x + threadIdx.x) >> 5;
    int lane = threadIdx.x & 31;
    if (gw >= NNODES) return;
    const uint2* __restrict__ t = (const uint2*)tmp;
    float di = g_dinv[gw];
    float s = di * di;
    uint2 u = t[gw * 32 + lane];
    float2 p0 = __half22float2(*(__half2*)&u.x);
    float2 p1 = __half22float2(*(__half2*)&u.y);
    float4 acc = make_float4(p0.x * s, p0.y * s, p1.x * s, p1.y * s);
    float4 acc2 = make_float4(0.f, 0.f, 0.f, 0.f);
    int e = g_rowptr[gw], en = g_rowptr[gw + 1];
    for (; e < en; e += 8) {
        int cidx[8];
        float wv[8];
        uint2 v[8];
#pragma unroll
        for (int j = 0; j < 8; j++) {
            int ok = (e + j < en);
            int idx = ok ? (e + j) : e;
            cidx[j] = g_col[idx];
            wv[j] = ok ? g_w[idx] : 0.f;
        }
#pragma unroll
        for (int j = 0; j < 8; j++) v[j] = t[cidx[j] * 32 + lane];
#pragma unroll
        for (int j = 0; j < 8; j++) {
            float2 f0 = __half22float2(*(__half2*)&v[j].x);
            float2 f1 = __half22float2(*(__half2*)&v[j].y);
            if (j & 1) {
                acc2.x = fmaf(wv[j], f0.x, acc2.x); acc2.y = fmaf(wv[j], f0.y, acc2.y);
                acc2.z = fmaf(wv[j], f1.x, acc2.z); acc2.w = fmaf(wv[j], f1.y, acc2.w);
            } else {
                acc.x = fmaf(wv[j], f0.x, acc.x); acc.y = fmaf(wv[j], f0.y, acc.y);
                acc.z = fmaf(wv[j], f1.x, acc.z); acc.w = fmaf(wv[j], f1.y, acc.w);
            }
        }
    }
    acc.x += acc2.x; acc.y += acc2.y; acc.z += acc2.z; acc.w += acc2.w;

    size_t base = (size_t)gw * HID + lane * 4;
    if (PRE) {
        __half2 q0 = __floats2half2_rn(acc.x, acc.y);
        __half2 q1 = __floats2half2_rn(acc.z, acc.w);
        *(uint2*)&pfh[base] = make_uint2(*(uint32_t*)&q0, *(uint32_t*)&q1);
    }
    __half2 r0 = __floats2half2_rn(fmaxf(acc.x, 0.f), fmaxf(acc.y, 0.f));
    __half2 r1 = __floats2half2_rn(fmaxf(acc.z, 0.f), fmaxf(acc.w, 0.f));
    *(uint2*)&hf[base] = make_uint2(*(uint32_t*)&r0, *(uint32_t*)&r1);
}

// D=64 aggregation into d_out (fp32) + fp16 copy for the gram
__global__ void k_agg64h(const __half* __restrict__ tmp, float* __restrict__ out,
                         __half* __restrict__ cpy) {
    int gw = (blockIdx.x * blockDim.x + threadIdx.x) >> 5;
    int lane = threadIdx.x & 31;
    if (gw >= NNODES) return;
    const uint32_t* __restrict__ t = (const uint32_t*)tmp;
    float di = g_dinv[gw];
    float s = di * di;
    uint32_t u = t[gw * 32 + lane];
    float2 p = __half22float2(*(__half2*)&u);
    float2 acc = make_float2(p.x * s, p.y * s);
    float2 acc2 = make_float2(0.f, 0.f);
    int e = g_rowptr[gw], en = g_rowptr[gw + 1];
    for (; e < en; e += 8) {
        int cidx[8];
        float wv[8];
        uint32_t v[8];
#pragma unroll
        for (int j = 0; j < 8; j++) {
            int ok = (e + j < en);
            int idx = ok ? (e + j) : e;
            cidx[j] = g_col[idx];
            wv[j] = ok ? g_w[idx] : 0.f;
        }
#pragma unroll
        for (int j = 0; j < 8; j++) v[j] = t[cidx[j] * 32 + lane];
#pragma unroll
        for (int j = 0; j < 8; j++) {
            float2 f = __half22float2(*(__half2*)&v[j]);
            if (j & 1) {
                acc2.x = fmaf(wv[j], f.x, acc2.x); acc2.y = fmaf(wv[j], f.y, acc2.y);
            } else {
                acc.x = fmaf(wv[j], f.x, acc.x); acc.y = fmaf(wv[j], f.y, acc.y);
            }
        }
    }
    acc.x += acc2.x; acc.y += acc2.y;
    ((float2*)out)[gw * 32 + lane] = acc;
    __half2 q = __floats2half2_rn(acc.x, acc.y);
    ((uint32_t*)cpy)[gw * 32 + lane] = *(uint32_t*)&q;
}

// ---------------- Gram via mma from fp16 h (single term) --------------------
template <int D>
__global__ __launch_bounds__(256) void k_gram_h(const __half* __restrict__ hh,
                                                float* __restrict__ G,
                                                float* __restrict__ cs) {
    __shared__ __align__(1024) uint8_t sm[D * 128];
    const int FG = D / 4;
    const int PAIRS = 256 / FG;
    const int NT = D / 8;
    const int MW = D / 16;
    uint32_t sb = smem_u32(sm);
    int tid = threadIdx.x, wid = tid >> 5, lane = tid & 31;
    int f4 = tid % FG;
    int rp0 = tid / FG;

    float acc[NT][4];
#pragma unroll
    for (int j = 0; j < NT; j++)
#pragma unroll
        for (int q = 0; q < 4; q++) acc[j][q] = 0.f;
    float cs0 = 0.f, cs1 = 0.f, cs2 = 0.f, cs3 = 0.f;

    const int NCHUNK = (NNODES + 63) / 64;
    for (int ch = blockIdx.x; ch < NCHUNK; ch += gridDim.x) {
        int rbase = ch * 64;
#pragma unroll
        for (int it = 0; it < 32 / PAIRS; it++) {
            int pr = rp0 + it * PAIRS;
            int r0 = rbase + pr * 2, r1 = r0 + 1;
            uint2 h0v = make_uint2(0, 0), h1v = h0v;
            if (r0 < NNODES) h0v = *(const uint2*)&hh[(size_t)r0 * D + f4 * 4];
            if (r1 < NNODES) h1v = *(const uint2*)&hh[(size_t)r1 * D + f4 * 4];
            const ushort* h0s = (const ushort*)&h0v;
            const ushort* h1s = (const ushort*)&h1v;
#pragma unroll
            for (int j = 0; j < 4; j++) {
                float f0 = __half2float(__ushort_as_half(h0s[j]));
                float f1 = __half2float(__ushort_as_half(h1s[j]));
                float fs = f0 + f1;
                if (j == 0) cs0 += fs;
                else if (j == 1) cs1 += fs;
                else if (j == 2) cs2 += fs;
                else cs3 += fs;
                int feat = f4 * 4 + j;
                uint32_t hp = (uint32_t)h0s[j] | ((uint32_t)h1s[j] << 16);
                uint32_t so = sw128((uint32_t)(feat * 128 + pr * 4));
                *(uint32_t*)(sm + so) = hp;
            }
        }
        __syncthreads();
        if (wid < MW) {
#pragma unroll
            for (int k16 = 0; k16 < 4; k16++) {
                int kb = k16 * 32;
                uint32_t av[4];
                {
                    int r = wid * 16 + (lane & 15);
                    int cb = kb + ((lane & 16) ? 16 : 0);
                    uint32_t so = sw128((uint32_t)(r * 128 + cb));
                    ldsm4(av, sb + so);
                }
#pragma unroll
                for (int bt = 0; bt < NT / 2; bt++) {
                    int n = bt * 16 + (lane & 7) + ((lane & 16) ? 8 : 0);
                    int cb = kb + ((lane & 8) ? 16 : 0);
                    uint32_t so = sw128((uint32_t)(n * 128 + cb));
                    uint32_t bv[4];
                    ldsm4(bv, sb + so);
#pragma unroll
                    for (int h2 = 0; h2 < 2; h2++) {
                        int nt = bt * 2 + h2;
                        mma_h(acc[nt], av, &bv[h2 * 2]);
                    }
                }
            }
        }
        __syncthreads();
    }
    if (wid < MW) {
        int mrow = wid * 16 + (lane >> 2);
#pragma unroll
        for (int nt = 0; nt < NT; nt++) {
            int c = nt * 8 + (lane & 3) * 2;
            atomicAdd(&G[mrow * D + c], acc[nt][0]);
            atomicAdd(&G[mrow * D + c + 1], acc[nt][1]);
            atomicAdd(&G[(mrow + 8) * D + c], acc[nt][2]);
            atomicAdd(&G[(mrow + 8) * D + c + 1], acc[nt][3]);
        }
    }
    atomicAdd(&cs[f4 * 4 + 0], cs0);
    atomicAdd(&cs[f4 * 4 + 1], cs1);
    atomicAdd(&cs[f4 * 4 + 2], cs2);
    atomicAdd(&cs[f4 * 4 + 3], cs3);
}

// ---------------- correlation metric finalize (single block) ----------------
template <int D>
__global__ void k_finalize(const float* __restrict__ G,
                           const float* __restrict__ cs,
                           float* __restrict__ dst) {
    __shared__ float sd[D];
    __shared__ float red[256];
    int tid = threadIdx.x;
    const float invN = 1.0f / (float)NNODES;
    if (tid < D) {
        float cjj = G[tid * D + tid] - cs[tid] * cs[tid] * invN;
        sd[tid] = sqrtf(fmaxf(cjj, 1e-12f));
    }
    __syncthreads();
    float sum = 0.f;
    for (int idx = tid; idx < D * D; idx += 256) {
        int j = idx / D, k = idx % D;
        if (k > j) {
            float cov = G[idx] - cs[j] * cs[k] * invN;
            sum += fabsf(cov / (sd[j] * sd[k]));
        }
    }
    red[tid] = sum;
    __syncthreads();
    for (int off = 128; off > 0; off >>= 1) {
        if (tid < off) red[tid] += red[tid + off];
        __syncthreads();
    }
    if (tid == 0) *dst = red[0] / (float)(D * (D - 1) / 2);
}

// ---------------- launch ----------------
extern "C" void kernel_launch(void* const* d_in, const int* in_sizes, int n_in,
                              void* d_out, int out_size) {
    const float* x  = (const float*)d_in[0];
    const int*   ei = (const int*)d_in[1];
    const float* W0 = (const float*)d_in[2];
    const float* W1 = (const float*)d_in[3];
    const float* W2 = (const float*)d_in[4];
    const float* W3 = (const float*)d_in[5];
    float* out = (float*)d_out;

    __half *tmp, *hf, *pfh;
    cudaGetSymbolAddress((void**)&tmp, g_tmp);
    cudaGetSymbolAddress((void**)&hf, g_hf);
    cudaGetSymbolAddress((void**)&pfh, g_pf);
    __half *w0h, *w0l, *w1h, *w1l, *w2h, *w2l, *w3h, *w3l;
    cudaGetSymbolAddress((void**)&w0h, g_w0h); cudaGetSymbolAddress((void**)&w0l, g_w0l);
    cudaGetSymbolAddress((void**)&w1h, g_w1h); cudaGetSymbolAddress((void**)&w1l, g_w1l);
    cudaGetSymbolAddress((void**)&w2h, g_w2h); cudaGetSymbolAddress((void**)&w2l, g_w2l);
    cudaGetSymbolAddress((void**)&w3h, g_w3h); cudaGetSymbolAddress((void**)&w3l, g_w3l);
    int *cntp, *curp;
    float *Gp, *csp, *G2p, *cs2p;
    cudaGetSymbolAddress((void**)&cntp, g_cnt);
    cudaGetSymbolAddress((void**)&curp, g_cursor);
    cudaGetSymbolAddress((void**)&Gp, g_G);
    cudaGetSymbolAddress((void**)&csp, g_csum);
    cudaGetSymbolAddress((void**)&G2p, g_G2);
    cudaGetSymbolAddress((void**)&cs2p, g_csum2);

    const int SM_BIG = 2 * 128 * 128 + 4 * HID * 128;   // 98304
    const int SM_SML = 2 * 128 * 128 + 4 * COUT * 128;  // 65536
    cudaFuncSetAttribute((const void*)k_tgemm512<FIN, HID, true, 2>,
                         cudaFuncAttributeMaxDynamicSharedMemorySize, SM_BIG);
    cudaFuncSetAttribute((const void*)k_tgemm512<HID, HID, false, 2>,
                         cudaFuncAttributeMaxDynamicSharedMemorySize, SM_BIG);
    cudaFuncSetAttribute((const void*)k_tgemm512<HID, COUT, false, 2>,
                         cudaFuncAttributeMaxDynamicSharedMemorySize, SM_SML);

    // side stream + events for fork/join inside graph capture (leaked, bounded)
    cudaStream_t s1;
    cudaStreamCreateWithFlags(&s1, cudaStreamNonBlocking);
    cudaEvent_t eFork1, ePre, eFork2, eCorr;
    cudaEventCreateWithFlags(&eFork1, cudaEventDisableTiming);
    cudaEventCreateWithFlags(&ePre,  cudaEventDisableTiming);
    cudaEventCreateWithFlags(&eFork2, cudaEventDisableTiming);
    cudaEventCreateWithFlags(&eCorr, cudaEventDisableTiming);

    const int TB = 256;
    const int nbE = (NEDGES + TB - 1) / TB;
    const int nbM = (NNODES + 127) / 128;
    const int nbA = (NNODES + 7) / 8;
    const int P3N = 2 * HID * HID + HID * COUT;

    // ---- fork: preprocessing on s1, L0 GEMM path on capture stream ----
    cudaEventRecord(eFork1, 0);
    cudaStreamWaitEvent(s1, eFork1, 0);

    cudaMemsetAsync(G2p, 0, COUT * COUT * sizeof(float), 0);
    cudaMemsetAsync(cs2p, 0, COUT * sizeof(float), 0);
    k_prepW<FIN, HID><<<(FIN * HID + TB - 1) / TB, TB>>>(W0, w0h, w0l);
    cudaMemsetAsync(cntp, 0, NNODES * sizeof(int), s1);
    cudaMemsetAsync(curp, 0, NNODES * sizeof(int), s1);
    k_count<<<nbE, TB, 0, s1>>>(ei);
    k_tgemm512<FIN, HID, true, 2><<<nbM, 512, SM_BIG>>>(x, nullptr,
                                                        w0h, w0l, tmp);
    k_scan1<<<SCAN_NB, SCAN_TPB, 0, s1>>>();
    k_scan2<<<1, 64, 0, s1>>>();
    k_scan3<<<SCAN_NB, SCAN_TPB, 0, s1>>>();
    k_fill<<<nbE, TB, 0, s1>>>(ei);
    k_prepW3x<<<(P3N + TB - 1) / TB, TB, 0, s1>>>(W1, W2, W3);
    cudaEventRecord(ePre, s1);
    cudaStreamWaitEvent(0, ePre, 0);

    // layer 0 aggregation -> relu'd fp16 h0
    k_agg128s<false><<<nbA, TB>>>(tmp, hf, pfh);
    // layer 1
    k_tgemm512<HID, HID, false, 2><<<nbM, 512, SM_BIG>>>(nullptr, hf, w1h, w1l, tmp);
    k_agg128s<false><<<nbA, TB>>>(tmp, hf, pfh);
    // layer 2 (pre-relu h2 kept as fp16 for corr_2)
    k_tgemm512<HID, HID, false, 2><<<nbM, 512, SM_BIG>>>(nullptr, hf, w2h, w2l, tmp);
    k_agg128s<true><<<nbA, TB>>>(tmp, hf, pfh);

    // ---- fork: corr_2 metric (s1, uses g_G) concurrent with layer-3 (s0) ----
    cudaEventRecord(eFork2, 0);
    cudaStreamWaitEvent(s1, eFork2, 0);
    cudaMemsetAsync(Gp, 0, HID * HID * sizeof(float), s1);
    cudaMemsetAsync(csp, 0, HID * sizeof(float), s1);
    k_gram_h<HID><<<296, 256, 0, s1>>>(pfh, Gp, csp);
    k_finalize<HID><<<1, 256, 0, s1>>>(Gp, csp, out + NNODES * COUT);
    cudaEventRecord(eCorr, s1);

    // layer 3: relu(h2) @ W3 -> agg into d_out (+fp16 copy into dead hf)
    k_tgemm512<HID, COUT, false, 2><<<nbM, 512, SM_SML>>>(nullptr, hf, w3h, w3l, tmp);
    k_agg64h<<<nbA, TB>>>(tmp, out, hf);

    // final corr on h3 (uses independent g_G2 — no wait on corr_2)
    k_gram_h<COUT><<<296, 256>>>(hf, G2p, cs2p);
    k_finalize<COUT><<<1, 256>>>(G2p, cs2p, out + NNODES * COUT + 1);

    // join s1 back into the capture stream (required for valid capture)
    cudaStreamWaitEvent(0, eCorr, 0);
}

// round 16
// speedup vs baseline: 1.1183x; 1.1183x over previous
#include <cuda_runtime.h>
#include <cuda_bf16.h>
#include <cuda_fp16.h>
#include <math.h>
#include <stdint.h>

#define NNODES 100000
#define NEDGES 1600000
#define FIN 256
#define HID 128
#define COUT 64

#define SCAN_TPB 256
#define SCAN_ELEMS 8
#define SCAN_CHUNK (SCAN_TPB * SCAN_ELEMS)                 // 2048
#define SCAN_NB ((NNODES + SCAN_CHUNK - 1) / SCAN_CHUNK)   // 49

// ---------------- scratch (static __device__, no allocation) ----------------
__device__ __half g_tmp[NNODES * HID];          // messages (GEMM out), fp16
__device__ __half g_hf[NNODES * HID];           // relu'd h fp16 (GEMM A) / h3 fp16 copy
__device__ __half g_pf[NNODES * HID];           // pre-relu h2 fp16 (gram operand)
__device__ float g_dinv[NNODES];
__device__ int   g_cnt[NNODES];
__device__ int   g_cursor[NNODES];
__device__ int   g_rowptr[NNODES + 1];
__device__ int2  g_cw[NEDGES];                  // interleaved (col, w-bits)
__device__ float g_G[HID * HID];
__device__ float g_csum[HID];
__device__ float g_G2[COUT * COUT];
__device__ float g_csum2[COUT];
__device__ int   g_bsum[SCAN_NB];

// split-fp16 transposed weights: Wt[d][k] = W[k][d]
__device__ __half g_w0h[HID * FIN],  g_w0l[HID * FIN];
__device__ __half g_w1h[HID * HID],  g_w1l[HID * HID];
__device__ __half g_w2h[HID * HID],  g_w2l[HID * HID];
__device__ __half g_w3h[COUT * HID], g_w3l[COUT * HID];

// ---------------- helpers ----------------
__device__ __forceinline__ uint32_t smem_u32(const void* p) {
    uint32_t a;
    asm("{ .reg .u64 t; cvta.to.shared.u64 t, %1; cvt.u32.u64 %0, t; }"
        : "=r"(a) : "l"(p));
    return a;
}
__device__ __forceinline__ uint32_t sw128(uint32_t off) {
    return off ^ ((off >> 3) & 0x70);
}
__device__ __forceinline__ void ldsm4(uint32_t* r, uint32_t addr) {
    asm volatile("ldmatrix.sync.aligned.m8n8.x4.shared.b16 {%0,%1,%2,%3}, [%4];"
                 : "=r"(r[0]), "=r"(r[1]), "=r"(r[2]), "=r"(r[3]) : "r"(addr));
}
__device__ __forceinline__ void mma_h(float* c, const uint32_t* a,
                                      const uint32_t* b) {
    asm volatile(
        "mma.sync.aligned.m16n8k16.row.col.f32.f16.f16.f32 "
        "{%0,%1,%2,%3}, {%4,%5,%6,%7}, {%8,%9}, {%0,%1,%2,%3};"
        : "+f"(c[0]), "+f"(c[1]), "+f"(c[2]), "+f"(c[3])
        : "r"(a[0]), "r"(a[1]), "r"(a[2]), "r"(a[3]), "r"(b[0]), "r"(b[1]));
}
__device__ __forceinline__ void split2h(float f, __half& h, __half& l) {
    h = __float2half_rn(f);
    l = __float2half_rn(f - __half2float(h));
}
__device__ __forceinline__ void cpa16(uint32_t dst, const void* src, int nbytes) {
    asm volatile("cp.async.cg.shared.global [%0], [%1], 16, %2;"
                 :: "r"(dst), "l"(src), "r"(nbytes) : "memory");
}
__device__ __forceinline__ void cpa_commit() {
    asm volatile("cp.async.commit_group;" ::: "memory");
}
__device__ __forceinline__ void cpa_wait1() {
    asm volatile("cp.async.wait_group 1;" ::: "memory");
}
__device__ __forceinline__ void cpa_wait0() {
    asm volatile("cp.async.wait_group 0;" ::: "memory");
}

// ---------------- preprocessing ----------------
__global__ void k_count(const int* __restrict__ ei) {
    int e = blockIdx.x * blockDim.x + threadIdx.x;
    if (e < NEDGES) atomicAdd(&g_cnt[ei[e]], 1);
}

__global__ void k_scan1() {
    __shared__ int warp_s[SCAN_TPB / 32];
    int tid = threadIdx.x, blk = blockIdx.x;
    int base = blk * SCAN_CHUNK + tid * SCAN_ELEMS;
    int s = 0;
#pragma unroll
    for (int i = 0; i < SCAN_ELEMS; i++) {
        int idx = base + i;
        if (idx < NNODES) {
            int c = g_cnt[idx];
            s += c;
            g_dinv[idx] = rsqrtf((float)(c + 1));  // +1 self loop
        }
    }
    for (int o = 16; o > 0; o >>= 1) s += __shfl_down_sync(0xffffffffu, s, o);
    if ((tid & 31) == 0) warp_s[tid >> 5] = s;
    __syncthreads();
    if (tid < SCAN_TPB / 32) {
        int w = warp_s[tid];
        for (int o = (SCAN_TPB / 64); o > 0; o >>= 1)
            w += __shfl_down_sync(0xffu, w, o);
        if (tid == 0) g_bsum[blk] = w;
    }
}

__global__ void k_scan2() {
    __shared__ int sh[64];
    int tid = threadIdx.x;
    sh[tid] = (tid < SCAN_NB) ? g_bsum[tid] : 0;
    __syncthreads();
    for (int o = 1; o < 64; o <<= 1) {
        int v = (tid >= o) ? sh[tid - o] : 0;
        __syncthreads();
        sh[tid] += v;
        __syncthreads();
    }
    if (tid < SCAN_NB) g_bsum[tid] = (tid == 0) ? 0 : sh[tid - 1];
    if (tid == 0) g_rowptr[NNODES] = sh[SCAN_NB - 1];
}

__global__ void k_scan3() {
    __shared__ int tsum[SCAN_TPB];
    int tid = threadIdx.x, blk = blockIdx.x;
    int base = blk * SCAN_CHUNK + tid * SCAN_ELEMS;
    int c[SCAN_ELEMS];
    int s = 0;
#pragma unroll
    for (int i = 0; i < SCAN_ELEMS; i++) {
        int idx = base + i;
        c[i] = (idx < NNODES) ? g_cnt[idx] : 0;
        s += c[i];
    }
    tsum[tid] = s;
    __syncthreads();
    for (int o = 1; o < SCAN_TPB; o <<= 1) {
        int v = (tid >= o) ? tsum[tid - o] : 0;
        __syncthreads();
        tsum[tid] += v;
        __syncthreads();
    }
    int run = g_bsum[blk] + ((tid == 0) ? 0 : tsum[tid - 1]);
#pragma unroll
    for (int i = 0; i < SCAN_ELEMS; i++) {
        int idx = base + i;
        if (idx < NNODES) { g_rowptr[idx] = run; run += c[i]; }
    }
}

__global__ void k_fill(const int* __restrict__ ei) {
    int e = blockIdx.x * blockDim.x + threadIdx.x;
    if (e >= NEDGES) return;
    int r = ei[e];
    int c = ei[NEDGES + e];
    int pos = g_rowptr[r] + atomicAdd(&g_cursor[r], 1);
    float w = g_dinv[r] * g_dinv[c];
    g_cw[pos] = make_int2(c, __float_as_int(w));
}

// ---------------- weight prep: W[K,D] fp32 -> Wt hi/lo fp16 [D][K] ----------
template <int K, int D>
__global__ void k_prepW(const float* __restrict__ W,
                        __half* __restrict__ Wh, __half* __restrict__ Wl) {
    int i = blockIdx.x * blockDim.x + threadIdx.x;
    if (i >= K * D) return;
    int n = i / K, k = i % K;
    __half h, l;
    split2h(W[k * D + n], h, l);
    Wh[n * K + k] = h;
    Wl[n * K + k] = l;
}

__global__ void k_prepW3x(const float* __restrict__ W1,
                          const float* __restrict__ W2,
                          const float* __restrict__ W3) {
    int i = blockIdx.x * blockDim.x + threadIdx.x;
    const int S1 = HID * HID, S2 = 2 * HID * HID, S3 = 2 * HID * HID + HID * COUT;
    __half h, l;
    if (i < S1) {
        int n = i / HID, k = i % HID;
        split2h(W1[k * HID + n], h, l);
        g_w1h[n * HID + k] = h; g_w1l[n * HID + k] = l;
    } else if (i < S2) {
        int j = i - S1;
        int n = j / HID, k = j % HID;
        split2h(W2[k * HID + n], h, l);
        g_w2h[n * HID + k] = h; g_w2l[n * HID + k] = l;
    } else if (i < S3) {
        int j = i - S2;
        int n = j / HID, k = j % HID;
        split2h(W3[k * COUT + n], h, l);
        g_w3h[n * HID + k] = h; g_w3l[n * HID + k] = l;
    }
}

// ---------------- fp16-A / split-fp16-B GEMM --------------------------------
template <int K, int D, bool CONVERT, int MINB>
__global__ __launch_bounds__(512, MINB) void k_tgemm512(const float* __restrict__ Af,
                                                        const __half* __restrict__ Ah,
                                                        const __half* __restrict__ Bh,
                                                        const __half* __restrict__ Bl,
                                                        __half* __restrict__ C) {
    extern __shared__ __align__(1024) uint8_t smem[];
    const int CK = 64;
    const int NCH = K / CK;
    const int WN = D / 4;
    const int NT = WN / 8;
    const int STA = 128 * 128;
    const int SBB = D * 128;
    const bool SINGLE = (!CONVERT) && (NCH <= 2);
    const int NSTA = SINGLE ? NCH : 2;
    const int OFF_B = NSTA * STA;

    uint32_t sb = smem_u32(smem);
    int tid = threadIdx.x, wid = tid >> 5, lane = tid & 31;
    int wm = wid & 3, wn = wid >> 2;
    int row0 = wm * 32;
    int col0 = wn * WN;
    int grow = blockIdx.x * 128;

    float acc[2][NT][4];
#pragma unroll
    for (int i = 0; i < 2; i++)
#pragma unroll
        for (int j = 0; j < NT; j++)
#pragma unroll
            for (int q = 0; q < 4; q++) acc[i][j][q] = 0.f;

    auto a_async = [&](int s, int ch) {
        int kk = ch * CK;
#pragma unroll
        for (int i = 0; i < 2; i++) {
            int u = tid + i * 512;
            int m = u >> 3, g = u & 7;
            int r = grow + m;
            int rc = (r < NNODES) ? r : 0;
            int nb = (r < NNODES) ? 16 : 0;
            uint32_t so = sw128((uint32_t)(m * 128 + g * 16));
            cpa16(sb + s * STA + so, &Ah[(size_t)rc * K + kk + g * 8], nb);
        }
    };
    auto b_async = [&](int s, int ch) {
        int kk = ch * CK;
#pragma unroll
        for (int i = 0; i < (D * 8 + 511) / 512; i++) {
            int u = tid + i * 512;
            if (u < D * 8) {
                int n = u >> 3, g = u & 7;
                uint32_t so = sw128((uint32_t)(n * 128 + g * 16));
                cpa16(sb + OFF_B + (2 * s) * SBB + so, &Bh[n * K + kk + g * 8], 16);
                cpa16(sb + OFF_B + (2 * s + 1) * SBB + so, &Bl[n * K + kk + g * 8], 16);
            }
        }
    };
    auto a_direct = [&](int s, int ch) {
        int kk = ch * CK;
#pragma unroll
        for (int i = 0; i < 2; i++) {
            int u = tid + i * 512;
            int m = u >> 3, g = u & 7;
            int r = grow + m;
            float4 v0 = make_float4(0.f, 0.f, 0.f, 0.f), v1 = v0;
            if (r < NNODES) {
                const float* p = &Af[(size_t)r * K + kk + g * 8];
                v0 = *(const float4*)p;
                v1 = *(const float4*)(p + 4);
            }
            __half2 h0 = __floats2half2_rn(v0.x, v0.y);
            __half2 h1 = __floats2half2_rn(v0.z, v0.w);
            __half2 h2 = __floats2half2_rn(v1.x, v1.y);
            __half2 h3 = __floats2half2_rn(v1.z, v1.w);
            uint32_t so = sw128((uint32_t)(m * 128 + g * 16));
            *(uint4*)(smem + s * STA + so) =
                make_uint4(*(uint32_t*)&h0, *(uint32_t*)&h1,
                           *(uint32_t*)&h2, *(uint32_t*)&h3);
        }
    };
    auto mma_stage = [&](int stA, int stB) {
        uint32_t aB = sb + stA * STA;
        uint32_t bB0 = sb + OFF_B + (2 * stB) * SBB;
        uint32_t bB1 = sb + OFF_B + (2 * stB + 1) * SBB;
#pragma unroll
        for (int k16 = 0; k16 < CK / 16; k16++) {
            int kb = k16 * 32;
            uint32_t ah[2][4];
#pragma unroll
            for (int mt = 0; mt < 2; mt++) {
                int r = row0 + mt * 16 + (lane & 15);
                int cb = kb + ((lane & 16) ? 16 : 0);
                uint32_t so = sw128((uint32_t)(r * 128 + cb));
                ldsm4(ah[mt], aB + so);
            }
#pragma unroll
            for (int bt = 0; bt < NT / 2; bt++) {
                int n = col0 + bt * 16 + (lane & 7) + ((lane & 16) ? 8 : 0);
                int cb = kb + ((lane & 8) ? 16 : 0);
                uint32_t so = sw128((uint32_t)(n * 128 + cb));
                uint32_t bh[4], bl[4];
                ldsm4(bh, bB0 + so);
                ldsm4(bl, bB1 + so);
#pragma unroll
                for (int h = 0; h < 2; h++) {
                    int nt = bt * 2 + h;
#pragma unroll
                    for (int mt = 0; mt < 2; mt++) {
                        mma_h(acc[mt][nt], ah[mt], &bh[h * 2]);
                        mma_h(acc[mt][nt], ah[mt], &bl[h * 2]);
                    }
                }
            }
        }
    };

    if (SINGLE) {
#pragma unroll
        for (int s = 0; s < NCH; s++) { a_async(s, s); b_async(s, s); }
        cpa_commit();
        cpa_wait0();
        __syncthreads();
#pragma unroll
        for (int ch = 0; ch < NCH; ch++) mma_stage(ch, ch);
    } else {
        a_direct(0, 0);
        b_async(0, 0);
        cpa_commit();
        for (int ch = 0; ch < NCH; ch++) {
            int cur = ch & 1, nxt = cur ^ 1;
            bool more = (ch + 1 < NCH);
            if (more) {
                b_async(nxt, ch + 1);
                cpa_commit();
            }
            if (more) cpa_wait1(); else cpa_wait0();
            __syncthreads();
            mma_stage(cur, cur);
            if (more) a_direct(nxt, ch + 1);
            __syncthreads();
        }
    }

#pragma unroll
    for (int mt = 0; mt < 2; mt++) {
        int r0 = grow + row0 + mt * 16 + (lane >> 2);
        int r1 = r0 + 8;
#pragma unroll
        for (int nt = 0; nt < NT; nt++) {
            int cc = col0 + nt * 8 + (lane & 3) * 2;
            if (r0 < NNODES)
                *(__half2*)&C[(size_t)r0 * D + cc] =
                    __floats2half2_rn(acc[mt][nt][0], acc[mt][nt][1]);
            if (r1 < NNODES)
                *(__half2*)&C[(size_t)r1 * D + cc] =
                    __floats2half2_rn(acc[mt][nt][2], acc[mt][nt][3]);
        }
    }
}

// ---------------- sparse aggregation (fp16 gather, fp32 accumulate) --------
// Round-14 loop structure (8-wide body + 2 + 1 tails); interleaved (col,w).
template <bool PRE>
__global__ void k_agg128s(const __half* __restrict__ tmp,
                          __half* __restrict__ hf,
                          __half* __restrict__ pfh) {
    int gw = (blockIdx.x * blockDim.x + threadIdx.x) >> 5;
    int lane = threadIdx.x & 31;
    if (gw >= NNODES) return;
    const uint2* __restrict__ t = (const uint2*)tmp;
    float di = g_dinv[gw];
    float s = di * di;
    uint2 u = t[gw * 32 + lane];
    float2 p0 = __half22float2(*(__half2*)&u.x);
    float2 p1 = __half22float2(*(__half2*)&u.y);
    float4 acc = make_float4(p0.x * s, p0.y * s, p1.x * s, p1.y * s);
    float4 acc2 = make_float4(0.f, 0.f, 0.f, 0.f);
    int e = g_rowptr[gw], en = g_rowptr[gw + 1];
    for (; e + 7 < en; e += 8) {
        int2 cw[8];
        uint2 v[8];
#pragma unroll
        for (int j = 0; j < 8; j++) cw[j] = g_cw[e + j];
#pragma unroll
        for (int j = 0; j < 8; j++) v[j] = t[cw[j].x * 32 + lane];
#pragma unroll
        for (int j = 0; j < 8; j++) {
            float wv = __int_as_float(cw[j].y);
            float2 f0 = __half22float2(*(__half2*)&v[j].x);
            float2 f1 = __half22float2(*(__half2*)&v[j].y);
            if (j & 1) {
                acc2.x = fmaf(wv, f0.x, acc2.x); acc2.y = fmaf(wv, f0.y, acc2.y);
                acc2.z = fmaf(wv, f1.x, acc2.z); acc2.w = fmaf(wv, f1.y, acc2.w);
            } else {
                acc.x = fmaf(wv, f0.x, acc.x); acc.y = fmaf(wv, f0.y, acc.y);
                acc.z = fmaf(wv, f1.x, acc.z); acc.w = fmaf(wv, f1.y, acc.w);
            }
        }
    }
    for (; e + 1 < en; e += 2) {
        int2 c0 = g_cw[e], c1 = g_cw[e + 1];
        float w0 = __int_as_float(c0.y), w1 = __int_as_float(c1.y);
        uint2 a = t[c0.x * 32 + lane];
        uint2 b = t[c1.x * 32 + lane];
        float2 a0 = __half22float2(*(__half2*)&a.x), a1 = __half22float2(*(__half2*)&a.y);
        float2 b0 = __half22float2(*(__half2*)&b.x), b1 = __half22float2(*(__half2*)&b.y);
        acc.x = fmaf(w0, a0.x, acc.x);   acc.y = fmaf(w0, a0.y, acc.y);
        acc.z = fmaf(w0, a1.x, acc.z);   acc.w = fmaf(w0, a1.y, acc.w);
        acc2.x = fmaf(w1, b0.x, acc2.x); acc2.y = fmaf(w1, b0.y, acc2.y);
        acc2.z = fmaf(w1, b1.x, acc2.z); acc2.w = fmaf(w1, b1.y, acc2.w);
    }
    if (e < en) {
        int2 c0 = g_cw[e];
        float w0 = __int_as_float(c0.y);
        uint2 a = t[c0.x * 32 + lane];
        float2 a0 = __half22float2(*(__half2*)&a.x);
        float2 a1 = __half22float2(*(__half2*)&a.y);
        acc.x = fmaf(w0, a0.x, acc.x); acc.y = fmaf(w0, a0.y, acc.y);
        acc.z = fmaf(w0, a1.x, acc.z); acc.w = fmaf(w0, a1.y, acc.w);
    }
    acc.x += acc2.x; acc.y += acc2.y; acc.z += acc2.z; acc.w += acc2.w;

    size_t base = (size_t)gw * HID + lane * 4;
    if (PRE) {
        __half2 q0 = __floats2half2_rn(acc.x, acc.y);
        __half2 q1 = __floats2half2_rn(acc.z, acc.w);
        *(uint2*)&pfh[base] = make_uint2(*(uint32_t*)&q0, *(uint32_t*)&q1);
    }
    __half2 r0 = __floats2half2_rn(fmaxf(acc.x, 0.f), fmaxf(acc.y, 0.f));
    __half2 r1 = __floats2half2_rn(fmaxf(acc.z, 0.f), fmaxf(acc.w, 0.f));
    *(uint2*)&hf[base] = make_uint2(*(uint32_t*)&r0, *(uint32_t*)&r1);
}

// D=64 aggregation into d_out (fp32) + fp16 copy for the gram
__global__ void k_agg64h(const __half* __restrict__ tmp, float* __restrict__ out,
                         __half* __restrict__ cpy) {
    int gw = (blockIdx.x * blockDim.x + threadIdx.x) >> 5;
    int lane = threadIdx.x & 31;
    if (gw >= NNODES) return;
    const uint32_t* __restrict__ t = (const uint32_t*)tmp;
    float di = g_dinv[gw];
    float s = di * di;
    uint32_t u = t[gw * 32 + lane];
    float2 p = __half22float2(*(__half2*)&u);
    float2 acc = make_float2(p.x * s, p.y * s);
    float2 acc2 = make_float2(0.f, 0.f);
    int e = g_rowptr[gw], en = g_rowptr[gw + 1];
    for (; e + 7 < en; e += 8) {
        int2 cw[8];
        uint32_t v[8];
#pragma unroll
        for (int j = 0; j < 8; j++) cw[j] = g_cw[e + j];
#pragma unroll
        for (int j = 0; j < 8; j++) v[j] = t[cw[j].x * 32 + lane];
#pragma unroll
        for (int j = 0; j < 8; j++) {
            float wv = __int_as_float(cw[j].y);
            float2 f = __half22float2(*(__half2*)&v[j]);
            if (j & 1) {
                acc2.x = fmaf(wv, f.x, acc2.x); acc2.y = fmaf(wv, f.y, acc2.y);
            } else {
                acc.x = fmaf(wv, f.x, acc.x); acc.y = fmaf(wv, f.y, acc.y);
            }
        }
    }
    for (; e < en; e++) {
        int2 c0 = g_cw[e];
        float w0 = __int_as_float(c0.y);
        uint32_t a = t[c0.x * 32 + lane];
        float2 af = __half22float2(*(__half2*)&a);
        acc.x = fmaf(w0, af.x, acc.x); acc.y = fmaf(w0, af.y, acc.y);
    }
    acc.x += acc2.x; acc.y += acc2.y;
    ((float2*)out)[gw * 32 + lane] = acc;
    __half2 q = __floats2half2_rn(acc.x, acc.y);
    ((uint32_t*)cpy)[gw * 32 + lane] = *(uint32_t*)&q;
}

// ---------------- Gram via mma from fp16 h (single term) --------------------
template <int D>
__global__ __launch_bounds__(256) void k_gram_h(const __half* __restrict__ hh,
                                                float* __restrict__ G,
                                                float* __restrict__ cs) {
    __shared__ __align__(1024) uint8_t sm[D * 128];
    const int FG = D / 4;
    const int PAIRS = 256 / FG;
    const int NT = D / 8;
    const int MW = D / 16;
    uint32_t sb = smem_u32(sm);
    int tid = threadIdx.x, wid = tid >> 5, lane = tid & 31;
    int f4 = tid % FG;
    int rp0 = tid / FG;

    float acc[NT][4];
#pragma unroll
    for (int j = 0; j < NT; j++)
#pragma unroll
        for (int q = 0; q < 4; q++) acc[j][q] = 0.f;
    float cs0 = 0.f, cs1 = 0.f, cs2 = 0.f, cs3 = 0.f;

    const int NCHUNK = (NNODES + 63) / 64;
    for (int ch = blockIdx.x; ch < NCHUNK; ch += gridDim.x) {
        int rbase = ch * 64;
#pragma unroll
        for (int it = 0; it < 32 / PAIRS; it++) {
            int pr = rp0 + it * PAIRS;
            int r0 = rbase + pr * 2, r1 = r0 + 1;
            uint2 h0v = make_uint2(0, 0), h1v = h0v;
            if (r0 < NNODES) h0v = *(const uint2*)&hh[(size_t)r0 * D + f4 * 4];
            if (r1 < NNODES) h1v = *(const uint2*)&hh[(size_t)r1 * D + f4 * 4];
            const ushort* h0s = (const ushort*)&h0v;
            const ushort* h1s = (const ushort*)&h1v;
#pragma unroll
            for (int j = 0; j < 4; j++) {
                float f0 = __half2float(__ushort_as_half(h0s[j]));
                float f1 = __half2float(__ushort_as_half(h1s[j]));
                float fs = f0 + f1;
                if (j == 0) cs0 += fs;
                else if (j == 1) cs1 += fs;
                else if (j == 2) cs2 += fs;
                else cs3 += fs;
                int feat = f4 * 4 + j;
                uint32_t hp = (uint32_t)h0s[j] | ((uint32_t)h1s[j] << 16);
                uint32_t so = sw128((uint32_t)(feat * 128 + pr * 4));
                *(uint32_t*)(sm + so) = hp;
            }
        }
        __syncthreads();
        if (wid < MW) {
#pragma unroll
            for (int k16 = 0; k16 < 4; k16++) {
                int kb = k16 * 32;
                uint32_t av[4];
                {
                    int r = wid * 16 + (lane & 15);
                    int cb = kb + ((lane & 16) ? 16 : 0);
                    uint32_t so = sw128((uint32_t)(r * 128 + cb));
                    ldsm4(av, sb + so);
                }
#pragma unroll
                for (int bt = 0; bt < NT / 2; bt++) {
                    int n = bt * 16 + (lane & 7) + ((lane & 16) ? 8 : 0);
                    int cb = kb + ((lane & 8) ? 16 : 0);
                    uint32_t so = sw128((uint32_t)(n * 128 + cb));
                    uint32_t bv[4];
                    ldsm4(bv, sb + so);
#pragma unroll
                    for (int h2 = 0; h2 < 2; h2++) {
                        int nt = bt * 2 + h2;
                        mma_h(acc[nt], av, &bv[h2 * 2]);
                    }
                }
            }
        }
        __syncthreads();
    }
    if (wid < MW) {
        int mrow = wid * 16 + (lane >> 2);
#pragma unroll
        for (int nt = 0; nt < NT; nt++) {
            int c = nt * 8 + (lane & 3) * 2;
            atomicAdd(&G[mrow * D + c], acc[nt][0]);
            atomicAdd(&G[mrow * D + c + 1], acc[nt][1]);
            atomicAdd(&G[(mrow + 8) * D + c], acc[nt][2]);
            atomicAdd(&G[(mrow + 8) * D + c + 1], acc[nt][3]);
        }
    }
    atomicAdd(&cs[f4 * 4 + 0], cs0);
    atomicAdd(&cs[f4 * 4 + 1], cs1);
    atomicAdd(&cs[f4 * 4 + 2], cs2);
    atomicAdd(&cs[f4 * 4 + 3], cs3);
}

// ---------------- correlation metric finalize (single block) ----------------
template <int D>
__global__ void k_finalize(const float* __restrict__ G,
                           const float* __restrict__ cs,
                           float* __restrict__ dst) {
    __shared__ float sd[D];
    __shared__ float red[256];
    int tid = threadIdx.x;
    const float invN = 1.0f / (float)NNODES;
    if (tid < D) {
        float cjj = G[tid * D + tid] - cs[tid] * cs[tid] * invN;
        sd[tid] = sqrtf(fmaxf(cjj, 1e-12f));
    }
    __syncthreads();
    float sum = 0.f;
    for (int idx = tid; idx < D * D; idx += 256) {
        int j = idx / D, k = idx % D;
        if (k > j) {
            float cov = G[idx] - cs[j] * cs[k] * invN;
            sum += fabsf(cov / (sd[j] * sd[k]));
        }
    }
    red[tid] = sum;
    __syncthreads();
    for (int off = 128; off > 0; off >>= 1) {
        if (tid < off) red[tid] += red[tid + off];
        __syncthreads();
    }
    if (tid == 0) *dst = red[0] / (float)(D * (D - 1) / 2);
}

// ---------------- launch ----------------
extern "C" void kernel_launch(void* const* d_in, const int* in_sizes, int n_in,
                              void* d_out, int out_size) {
    const float* x  = (const float*)d_in[0];
    const int*   ei = (const int*)d_in[1];
    const float* W0 = (const float*)d_in[2];
    const float* W1 = (const float*)d_in[3];
    const float* W2 = (const float*)d_in[4];
    const float* W3 = (const float*)d_in[5];
    float* out = (float*)d_out;

    __half *tmp, *hf, *pfh;
    cudaGetSymbolAddress((void**)&tmp, g_tmp);
    cudaGetSymbolAddress((void**)&hf, g_hf);
    cudaGetSymbolAddress((void**)&pfh, g_pf);
    __half *w0h, *w0l, *w1h, *w1l, *w2h, *w2l, *w3h, *w3l;
    cudaGetSymbolAddress((void**)&w0h, g_w0h); cudaGetSymbolAddress((void**)&w0l, g_w0l);
    cudaGetSymbolAddress((void**)&w1h, g_w1h); cudaGetSymbolAddress((void**)&w1l, g_w1l);
    cudaGetSymbolAddress((void**)&w2h, g_w2h); cudaGetSymbolAddress((void**)&w2l, g_w2l);
    cudaGetSymbolAddress((void**)&w3h, g_w3h); cudaGetSymbolAddress((void**)&w3l, g_w3l);
    int *cntp, *curp;
    float *Gp, *csp, *G2p, *cs2p;
    cudaGetSymbolAddress((void**)&cntp, g_cnt);
    cudaGetSymbolAddress((void**)&curp, g_cursor);
    cudaGetSymbolAddress((void**)&Gp, g_G);
    cudaGetSymbolAddress((void**)&csp, g_csum);
    cudaGetSymbolAddress((void**)&G2p, g_G2);
    cudaGetSymbolAddress((void**)&cs2p, g_csum2);

    const int SM_BIG = 2 * 128 * 128 + 4 * HID * 128;   // 98304
    const int SM_SML = 2 * 128 * 128 + 4 * COUT * 128;  // 65536
    cudaFuncSetAttribute((const void*)k_tgemm512<FIN, HID, true, 2>,
                         cudaFuncAttributeMaxDynamicSharedMemorySize, SM_BIG);
    cudaFuncSetAttribute((const void*)k_tgemm512<HID, HID, false, 2>,
                         cudaFuncAttributeMaxDynamicSharedMemorySize, SM_BIG);
    cudaFuncSetAttribute((const void*)k_tgemm512<HID, COUT, false, 2>,
                         cudaFuncAttributeMaxDynamicSharedMemorySize, SM_SML);

    // side stream + events for fork/join inside graph capture (leaked, bounded)
    cudaStream_t s1;
    cudaStreamCreateWithFlags(&s1, cudaStreamNonBlocking);
    cudaEvent_t eFork1, ePre, eFork2, eCorr;
    cudaEventCreateWithFlags(&eFork1, cudaEventDisableTiming);
    cudaEventCreateWithFlags(&ePre,  cudaEventDisableTiming);
    cudaEventCreateWithFlags(&eFork2, cudaEventDisableTiming);
    cudaEventCreateWithFlags(&eCorr, cudaEventDisableTiming);

    const int TB = 256;
    const int nbE = (NEDGES + TB - 1) / TB;
    const int nbM = (NNODES + 127) / 128;
    const int nbA = (NNODES + 7) / 8;
    const int P3N = 2 * HID * HID + HID * COUT;

    // ---- fork: preprocessing on s1, L0 GEMM path on capture stream ----
    cudaEventRecord(eFork1, 0);
    cudaStreamWaitEvent(s1, eFork1, 0);

    cudaMemsetAsync(G2p, 0, COUT * COUT * sizeof(float), 0);
    cudaMemsetAsync(cs2p, 0, COUT * sizeof(float), 0);
    k_prepW<FIN, HID><<<(FIN * HID + TB - 1) / TB, TB>>>(W0, w0h, w0l);
    cudaMemsetAsync(cntp, 0, NNODES * sizeof(int), s1);
    cudaMemsetAsync(curp, 0, NNODES * sizeof(int), s1);
    k_count<<<nbE, TB, 0, s1>>>(ei);
    k_tgemm512<FIN, HID, true, 2><<<nbM, 512, SM_BIG>>>(x, nullptr,
                                                        w0h, w0l, tmp);
    k_scan1<<<SCAN_NB, SCAN_TPB, 0, s1>>>();
    k_scan2<<<1, 64, 0, s1>>>();
    k_scan3<<<SCAN_NB, SCAN_TPB, 0, s1>>>();
    k_fill<<<nbE, TB, 0, s1>>>(ei);
    k_prepW3x<<<(P3N + TB - 1) / TB, TB, 0, s1>>>(W1, W2, W3);
    cudaEventRecord(ePre, s1);
    cudaStreamWaitEvent(0, ePre, 0);

    // layer 0 aggregation -> relu'd fp16 h0
    k_agg128s<false><<<nbA, TB>>>(tmp, hf, pfh);
    // layer 1
    k_tgemm512<HID, HID, false, 2><<<nbM, 512, SM_BIG>>>(nullptr, hf, w1h, w1l, tmp);
    k_agg128s<false><<<nbA, TB>>>(tmp, hf, pfh);
    // layer 2 (pre-relu h2 kept as fp16 for corr_2)
    k_tgemm512<HID, HID, false, 2><<<nbM, 512, SM_BIG>>>(nullptr, hf, w2h, w2l, tmp);
    k_agg128s<true><<<nbA, TB>>>(tmp, hf, pfh);

    // ---- fork: corr_2 metric (s1, uses g_G) concurrent with layer-3 (s0) ----
    cudaEventRecord(eFork2, 0);
    cudaStreamWaitEvent(s1, eFork2, 0);
    cudaMemsetAsync(Gp, 0, HID * HID * sizeof(float), s1);
    cudaMemsetAsync(csp, 0, HID * sizeof(float), s1);
    k_gram_h<HID><<<296, 256, 0, s1>>>(pfh, Gp, csp);
    k_finalize<HID><<<1, 256, 0, s1>>>(Gp, csp, out + NNODES * COUT);
    cudaEventRecord(eCorr, s1);

    // layer 3: relu(h2) @ W3 -> agg into d_out (+fp16 copy into dead hf)
    k_tgemm512<HID, COUT, false, 2><<<nbM, 512, SM_SML>>>(nullptr, hf, w3h, w3l, tmp);
    k_agg64h<<<nbA, TB>>>(tmp, out, hf);

    // final corr on h3 (uses independent g_G2 — no wait on corr_2)
    k_gram_h<COUT><<<296, 256>>>(hf, G2p, cs2p);
    k_finalize<COUT><<<1, 256>>>(G2p, cs2p, out + NNODES * COUT + 1);

    // join s1 back into the capture stream (required for valid capture)
    cudaStreamWaitEvent(0, eCorr, 0);
}